// round 10
// baseline (speedup 1.0000x reference)
#include <cuda_runtime.h>
#include <cuda_bf16.h>
#include <cstdint>
#include <math.h>

#define MM   16          // B*T
#define NN   5000
#define DIN  64
#define EE   80000
#define HC   128
#define E2   (EE + NN)   // 85000 with self loops
#define ROWS (MM * NN)   // 80000

// ---------------- scratch (no allocations allowed) ----------------
// feature buffers are NODE-major: row = n*MM + m
__device__ float g_xl[ROWS * HC];   // 41 MB
__device__ float g_xr[ROWS * HC];
__device__ float g_h [ROWS * HC];   // layer-1 output (node-major)
__device__ int   g_cnt[NN];
__device__ float g_wsum[NN];
__device__ int   g_rowoff[NN + 1];
__device__ int   g_fill[NN];
__device__ float g_selfw[NN];
__device__ int2  g_epk[E2];         // {src, bitcast(weight)}
// pre-split weights: [K x 256] = [Wl | Wr] in bf16 hi/lo
__device__ __nv_bfloat16 g_W1hi[DIN * 256], g_W1lo[DIN * 256];
__device__ __nv_bfloat16 g_W2hi[HC * 256],  g_W2lo[HC * 256];

// ---------------- preprocessing ----------------
__global__ void k_zero() {
    int i = blockIdx.x * blockDim.x + threadIdx.x;
    if (i < NN) { g_cnt[i] = 0; g_wsum[i] = 0.f; }
}

__global__ void k_deg(const int* __restrict__ ei, const float* __restrict__ ew) {
    int e = blockIdx.x * blockDim.x + threadIdx.x;
    if (e < EE) {
        int d = ei[EE + e];
        atomicAdd(&g_cnt[d], 1);
        atomicAdd(&g_wsum[d], ew[e]);
    }
}

// one block, 1024 threads: exclusive scan of (deg+1), self-loop weights
__global__ void k_scan() {
    __shared__ int sums[1024];
    int tid = threadIdx.x;
    int base = tid * 5;
    int loc[5];
    int s = 0;
#pragma unroll
    for (int j = 0; j < 5; j++) {
        int i = base + j;
        int d = (i < NN) ? (g_cnt[i] + 1) : 0;   // +1 for self loop
        loc[j] = s;
        s += d;
    }
    sums[tid] = s;
    __syncthreads();
    for (int off = 1; off < 1024; off <<= 1) {
        int v = (tid >= off) ? sums[tid - off] : 0;
        __syncthreads();
        sums[tid] += v;
        __syncthreads();
    }
    int excl = (tid == 0) ? 0 : sums[tid - 1];
#pragma unroll
    for (int j = 0; j < 5; j++) {
        int i = base + j;
        if (i < NN) {
            int o = excl + loc[j];
            g_rowoff[i] = o;
            g_fill[i]   = o;
            int c = g_cnt[i];
            g_selfw[i] = (c > 0) ? (g_wsum[i] / (float)c) : 0.f;
        }
    }
    if (tid == 1023) g_rowoff[NN] = sums[1023];
}

__global__ void k_scatter(const int* __restrict__ ei, const float* __restrict__ ew) {
    int i = blockIdx.x * blockDim.x + threadIdx.x;
    if (i < EE) {
        int d = ei[EE + i];
        int p = atomicAdd(&g_fill[d], 1);
        g_epk[p] = make_int2(ei[i], __float_as_int(ew[i]));
    } else if (i < E2) {
        int n = i - EE;
        int p = atomicAdd(&g_fill[n], 1);
        g_epk[p] = make_int2(n, __float_as_int(g_selfw[n]));
    }
}

// split [Wl | Wr] (each K x 128 fp32) into bf16 hi/lo [K x 256]
__global__ void k_wsplit(const float* __restrict__ Wl, const float* __restrict__ Wr,
                         __nv_bfloat16* __restrict__ hi, __nv_bfloat16* __restrict__ lo,
                         int total) {
    int i = blockIdx.x * blockDim.x + threadIdx.x;
    if (i >= total) return;
    int k = i >> 8;
    int n = i & 255;
    float v = (n < 128) ? Wl[(size_t)k * 128 + n] : Wr[(size_t)k * 128 + (n - 128)];
    __nv_bfloat16 h = __float2bfloat16(v);
    hi[i] = h;
    lo[i] = __float2bfloat16(v - __bfloat162float(h));
}

// ---------------- tensor-core helpers ----------------
__device__ __forceinline__ void ldsm4(unsigned* r, unsigned addr) {
    asm volatile("ldmatrix.sync.aligned.m8n8.x4.shared.b16 {%0,%1,%2,%3}, [%4];"
        : "=r"(r[0]), "=r"(r[1]), "=r"(r[2]), "=r"(r[3]) : "r"(addr));
}
__device__ __forceinline__ void ldsm4t(unsigned* r, unsigned addr) {
    asm volatile("ldmatrix.sync.aligned.m8n8.x4.trans.shared.b16 {%0,%1,%2,%3}, [%4];"
        : "=r"(r[0]), "=r"(r[1]), "=r"(r[2]), "=r"(r[3]) : "r"(addr));
}
__device__ __forceinline__ void mma_bf16(float* c, const unsigned* a, const unsigned* b) {
    asm volatile(
        "mma.sync.aligned.m16n8k16.row.col.f32.bf16.bf16.f32 "
        "{%0,%1,%2,%3}, {%4,%5,%6,%7}, {%8,%9}, {%0,%1,%2,%3};"
        : "+f"(c[0]), "+f"(c[1]), "+f"(c[2]), "+f"(c[3])
        : "r"(a[0]), "r"(a[1]), "r"(a[2]), "r"(a[3]), "r"(b[0]), "r"(b[1]));
}
__device__ __forceinline__ void bsplit(float x, __nv_bfloat16& h, __nv_bfloat16& l) {
    h = __float2bfloat16(x);
    l = __float2bfloat16(x - __bfloat162float(h));
}

// ---------------- projections: [xl | xr] = A @ [Wl | Wr] ----------------
// Tensor-core GEMM, bf16 2-term split (3 MMAs: hh + hl + lh) ~= fp32 accuracy.
// Block: 128 rows x 256 cols. Full B panel (all K, bf16 hi/lo pre-split) is
// staged in dynamic smem ONCE per block; then 4 row-tiles of 32 rows each run
// the K-loop with only A staging. 4x less B L2 traffic than 32-row blocks.
// 8 warps: warp = 16 rows x 64 cols within a row-tile.
// MAP==1: A rows are (m*NN+n) (raw x) -> output row n*MM+m. IN_H: read g_h.
#define ASTR 40
#define BSTR 264
template <int K, int MAP, int IN_H>
__global__ void __launch_bounds__(256) k_gemm(const float* __restrict__ Ain,
                                              const __nv_bfloat16* __restrict__ Whi,
                                              const __nv_bfloat16* __restrict__ Wlo) {
    extern __shared__ __align__(16) char dsm[];
    __nv_bfloat16* Bs_hi = (__nv_bfloat16*)dsm;                  // K * BSTR
    __nv_bfloat16* Bs_lo = Bs_hi + K * BSTR;                     // K * BSTR
    __nv_bfloat16* As_hi = Bs_lo + K * BSTR;                     // 32 * ASTR
    __nv_bfloat16* As_lo = As_hi + 32 * ASTR;                    // 32 * ASTR

    const float* __restrict__ A = IN_H ? (const float*)g_h : Ain;

    const int tid  = threadIdx.x;
    const int lane = tid & 31;
    const int w    = tid >> 5;
    const int mt   = w & 1;        // m-tile: rows mt*16..+15 of the row-tile's 32
    const int nq   = w >> 1;       // n-quarter: cols nq*64..+63 of the 256

    const unsigned ah_base = (unsigned)__cvta_generic_to_shared(As_hi);
    const unsigned al_base = (unsigned)__cvta_generic_to_shared(As_lo);
    const unsigned bh_base = (unsigned)__cvta_generic_to_shared(Bs_hi);
    const unsigned bl_base = (unsigned)__cvta_generic_to_shared(Bs_lo);

    // ---- stage FULL B panel once (pure 16B copies of pre-split bf16) ----
    {
        constexpr int SLOTS = K * 32;       // uint4 slots per array
#pragma unroll 4
        for (int idx = tid; idx < 2 * SLOTS; idx += 256) {
            int arr = idx >= SLOTS;
            int rem = arr ? idx - SLOTS : idx;
            int k   = rem >> 5;
            int c8  = (rem & 31) * 8;
            const __nv_bfloat16* src = (arr ? Wlo : Whi) + (size_t)k * 256 + c8;
            __nv_bfloat16* dst = (arr ? Bs_lo : Bs_hi) + k * BSTR + c8;
            *(uint4*)dst = *(const uint4*)src;
        }
    }
    __syncthreads();

    // staging maps for A
    const int sar = tid >> 3;            // A row 0..31
    const int sak = (tid & 7) * 4;       // A k-offset
    const unsigned a_row = (unsigned)(mt * 16 + (lane & 15));
    const unsigned a_coladd = (unsigned)((lane >> 4) << 3);
    const int bk_row = (lane & 7) + ((lane >> 3) & 1) * 8;
    const int b_nadd = (lane >> 4) << 3;

#pragma unroll 1
    for (int rt = 0; rt < 4; rt++) {
        const int row0 = blockIdx.x * 128 + rt * 32;

        float acc[8][4];
#pragma unroll
        for (int j = 0; j < 8; j++)
#pragma unroll
            for (int q = 0; q < 4; q++) acc[j][q] = 0.f;

#pragma unroll 1
        for (int kc = 0; kc < K; kc += 32) {
            if (rt | kc) __syncthreads();   // protect As from in-flight readers
            // ---- stage A chunk 32x32, split hi/lo ----
            {
                float4 v = *(const float4*)&A[(size_t)(row0 + sar) * K + kc + sak];
                __nv_bfloat16 h0, l0, h1, l1, h2, l2, h3, l3;
                bsplit(v.x, h0, l0); bsplit(v.y, h1, l1);
                bsplit(v.z, h2, l2); bsplit(v.w, h3, l3);
                __nv_bfloat16* ph = &As_hi[sar * ASTR + sak];
                __nv_bfloat16* pl = &As_lo[sar * ASTR + sak];
                ph[0] = h0; ph[1] = h1; ph[2] = h2; ph[3] = h3;
                pl[0] = l0; pl[1] = l1; pl[2] = l2; pl[3] = l3;
            }
            __syncthreads();

            // ---- compute: 2 k16 steps ----
#pragma unroll
            for (int kk = 0; kk < 32; kk += 16) {
                unsigned ah[4], al[4];
                unsigned aoff = (a_row * ASTR + (unsigned)kk + a_coladd) * 2u;
                ldsm4(ah, ah_base + aoff);
                ldsm4(al, al_base + aoff);

                unsigned bh[16], bl[16];
#pragma unroll
                for (int t2 = 0; t2 < 4; t2++) {
                    unsigned boff = ((unsigned)((kc + kk + bk_row) * BSTR + nq * 64 + t2 * 16 + b_nadd)) * 2u;
                    ldsm4t(&bh[t2 * 4], bh_base + boff);
                    ldsm4t(&bl[t2 * 4], bl_base + boff);
                }
#pragma unroll
                for (int j = 0; j < 8; j++) {
                    const unsigned* bhj = &bh[(j >> 1) * 4 + (j & 1) * 2];
                    const unsigned* blj = &bl[(j >> 1) * 4 + (j & 1) * 2];
                    mma_bf16(acc[j], ah, bhj);   // hi*hi
                    mma_bf16(acc[j], ah, blj);   // hi*lo
                    mma_bf16(acc[j], al, bhj);   // lo*hi
                }
            }
        }

        // ---- epilogue for this row-tile ----
        int lrow = mt * 16 + (lane >> 2);
        int lcol = 2 * (lane & 3);
#pragma unroll
        for (int half = 0; half < 2; half++) {
            int r = row0 + lrow + half * 8;
            int orow;
            if (MAP == 1) {
                int m = r / NN;
                int n = r - m * NN;
                orow  = n * MM + m;
            } else {
                orow = r;
            }
#pragma unroll
            for (int j = 0; j < 8; j++) {
                int c = nq * 64 + j * 8 + lcol;
                float* buf = (c < 128) ? g_xl : g_xr;
                int cc = (c < 128) ? c : c - 128;
                *(float2*)&buf[(size_t)orow * HC + cc] =
                    make_float2(acc[j][half * 2], acc[j][half * 2 + 1]);
            }
        }
    }
}

// ---------------- fused edge kernel: gather + online softmax + aggregate ----------------
// one warp per (dst, m). lane owns channels 4*lane..4*lane+3; lanes 0-15 head 0,
// 16-31 head 1. Two-edge unrolled with independent softmax states merged at end.
template <int LAYER2>
__global__ void __launch_bounds__(256) k_edge(const float* __restrict__ We,
                                              const float* __restrict__ att,
                                              const float* __restrict__ bias,
                                              float* __restrict__ out) {
    int warp = threadIdx.x >> 5;
    int lane = threadIdx.x & 31;
    int dst  = blockIdx.x >> 1;
    int m    = ((blockIdx.x & 1) << 3) | warp;

    float4 xi = *(const float4*)&g_xr[(size_t)(dst * MM + m) * HC + lane * 4];
    float4 we = *(const float4*)&We[lane * 4];
    float4 at = *(const float4*)&att[lane * 4];

    // dual softmax states
    float axA = 0.f, ayA = 0.f, azA = 0.f, awA = 0.f, mxA = -1e30f, dnA = 0.f;
    float axB = 0.f, ayB = 0.f, azB = 0.f, awB = 0.f, mxB = -1e30f, dnB = 0.f;

    int beg = g_rowoff[dst];
    int end = g_rowoff[dst + 1];

    int j = beg;
    for (; j + 1 < end; j += 2) {
        int2 eA = g_epk[j];
        int2 eB = g_epk[j + 1];
        float wA = __int_as_float(eA.y);
        float wB = __int_as_float(eB.y);
        float4 xjA = *(const float4*)&g_xl[(size_t)(eA.x * MM + m) * HC + lane * 4];
        float4 xjB = *(const float4*)&g_xl[(size_t)(eB.x * MM + m) * HC + lane * 4];

        float a0 = xi.x + xjA.x + wA * we.x;
        float a1 = xi.y + xjA.y + wA * we.y;
        float a2 = xi.z + xjA.z + wA * we.z;
        float a3 = xi.w + xjA.w + wA * we.w;
        float b0 = xi.x + xjB.x + wB * we.x;
        float b1 = xi.y + xjB.y + wB * we.y;
        float b2 = xi.z + xjB.z + wB * we.z;
        float b3 = xi.w + xjB.w + wB * we.w;
        a0 = (a0 > 0.f) ? a0 : 0.2f * a0;  b0 = (b0 > 0.f) ? b0 : 0.2f * b0;
        a1 = (a1 > 0.f) ? a1 : 0.2f * a1;  b1 = (b1 > 0.f) ? b1 : 0.2f * b1;
        a2 = (a2 > 0.f) ? a2 : 0.2f * a2;  b2 = (b2 > 0.f) ? b2 : 0.2f * b2;
        a3 = (a3 > 0.f) ? a3 : 0.2f * a3;  b3 = (b3 > 0.f) ? b3 : 0.2f * b3;

        float pA = a0 * at.x;  pA = fmaf(a1, at.y, pA);
        pA = fmaf(a2, at.z, pA);  pA = fmaf(a3, at.w, pA);
        float pB = b0 * at.x;  pB = fmaf(b1, at.y, pB);
        pB = fmaf(b2, at.z, pB);  pB = fmaf(b3, at.w, pB);

#pragma unroll
        for (int off = 1; off <= 8; off <<= 1) {
            pA += __shfl_xor_sync(0xffffffffu, pA, off);
            pB += __shfl_xor_sync(0xffffffffu, pB, off);
        }

        float nmA = fmaxf(mxA, pA);
        float nmB = fmaxf(mxB, pB);
        float scA = __expf(mxA - nmA);
        float scB = __expf(mxB - nmB);
        float eA_ = __expf(pA - nmA);
        float eB_ = __expf(pB - nmB);
        dnA = dnA * scA + eA_;          dnB = dnB * scB + eB_;
        axA = fmaf(eA_, xjA.x, axA * scA);  axB = fmaf(eB_, xjB.x, axB * scB);
        ayA = fmaf(eA_, xjA.y, ayA * scA);  ayB = fmaf(eB_, xjB.y, ayB * scB);
        azA = fmaf(eA_, xjA.z, azA * scA);  azB = fmaf(eB_, xjB.z, azB * scB);
        awA = fmaf(eA_, xjA.w, awA * scA);  awB = fmaf(eB_, xjB.w, awB * scB);
        mxA = nmA;  mxB = nmB;
    }
    if (j < end) {
        int2 eA = g_epk[j];
        float wA = __int_as_float(eA.y);
        float4 xjA = *(const float4*)&g_xl[(size_t)(eA.x * MM + m) * HC + lane * 4];
        float a0 = xi.x + xjA.x + wA * we.x;
        float a1 = xi.y + xjA.y + wA * we.y;
        float a2 = xi.z + xjA.z + wA * we.z;
        float a3 = xi.w + xjA.w + wA * we.w;
        a0 = (a0 > 0.f) ? a0 : 0.2f * a0;
        a1 = (a1 > 0.f) ? a1 : 0.2f * a1;
        a2 = (a2 > 0.f) ? a2 : 0.2f * a2;
        a3 = (a3 > 0.f) ? a3 : 0.2f * a3;
        float pA = a0 * at.x;  pA = fmaf(a1, at.y, pA);
        pA = fmaf(a2, at.z, pA);  pA = fmaf(a3, at.w, pA);
#pragma unroll
        for (int off = 1; off <= 8; off <<= 1)
            pA += __shfl_xor_sync(0xffffffffu, pA, off);
        float nmA = fmaxf(mxA, pA);
        float scA = __expf(mxA - nmA);
        float eA_ = __expf(pA - nmA);
        dnA = dnA * scA + eA_;
        axA = fmaf(eA_, xjA.x, axA * scA);
        ayA = fmaf(eA_, xjA.y, ayA * scA);
        azA = fmaf(eA_, xjA.z, azA * scA);
        awA = fmaf(eA_, xjA.w, awA * scA);
        mxA = nmA;
    }

    // merge state B into A (B may be empty: dnB=0 contributes nothing)
    float nm = fmaxf(mxA, mxB);
    float sA = __expf(mxA - nm);
    float sB = __expf(mxB - nm);
    float dn = dnA * sA + dnB * sB;
    float ax = axA * sA + axB * sB;
    float ay = ayA * sA + ayB * sB;
    float az = azA * sA + azB * sB;
    float aw = awA * sA + awB * sB;

    float inv = 1.f / (dn + 1e-16f);
    float4 b  = *(const float4*)&bias[lane * 4];
    float o0 = ax * inv + b.x;
    float o1 = ay * inv + b.y;
    float o2 = az * inv + b.z;
    float o3 = aw * inv + b.w;
    // ELU epilogue (both layers are followed by ELU in the reference)
    o0 = (o0 > 0.f) ? o0 : (__expf(o0) - 1.f);
    o1 = (o1 > 0.f) ? o1 : (__expf(o1) - 1.f);
    o2 = (o2 > 0.f) ? o2 : (__expf(o2) - 1.f);
    o3 = (o3 > 0.f) ? o3 : (__expf(o3) - 1.f);

    if (LAYER2) {
        *(float4*)&out[(size_t)(m * NN + dst) * HC + lane * 4] = make_float4(o0, o1, o2, o3);
    } else {
        *(float4*)&g_h[(size_t)(dst * MM + m) * HC + lane * 4] = make_float4(o0, o1, o2, o3);
    }
}

// ---------------- launch ----------------
extern "C" void kernel_launch(void* const* d_in, const int* in_sizes, int n_in,
                              void* d_out, int out_size) {
    const float* x    = (const float*)d_in[0];
    const int*   ei   = (const int*)d_in[1];
    const float* ew   = (const float*)d_in[2];
    const float* Wl1  = (const float*)d_in[3];
    const float* Wr1  = (const float*)d_in[4];
    const float* att1 = (const float*)d_in[5];
    const float* We1  = (const float*)d_in[6];
    const float* b1   = (const float*)d_in[7];
    const float* Wl2  = (const float*)d_in[8];
    const float* Wr2  = (const float*)d_in[9];
    const float* att2 = (const float*)d_in[10];
    const float* We2  = (const float*)d_in[11];
    const float* b2   = (const float*)d_in[12];
    float* out = (float*)d_out;

    __nv_bfloat16 *w1hi, *w1lo, *w2hi, *w2lo;
    cudaGetSymbolAddress((void**)&w1hi, g_W1hi);
    cudaGetSymbolAddress((void**)&w1lo, g_W1lo);
    cudaGetSymbolAddress((void**)&w2hi, g_W2hi);
    cudaGetSymbolAddress((void**)&w2lo, g_W2lo);

    // dynamic smem: B panel (hi+lo) + A tile (hi+lo)
    const int smem1 = (2 * DIN * BSTR + 2 * 32 * ASTR) * 2;   // K=64 -> ~72.7 KB
    const int smem2 = (2 * HC  * BSTR + 2 * 32 * ASTR) * 2;   // K=128 -> ~140 KB
    cudaFuncSetAttribute(k_gemm<DIN, 1, 0>, cudaFuncAttributeMaxDynamicSharedMemorySize, smem1);
    cudaFuncSetAttribute(k_gemm<HC, 0, 1>, cudaFuncAttributeMaxDynamicSharedMemorySize, smem2);

    k_zero<<<(NN + 255) / 256, 256>>>();
    k_deg<<<(EE + 255) / 256, 256>>>(ei, ew);
    k_scan<<<1, 1024>>>();
    k_scatter<<<(E2 + 255) / 256, 256>>>(ei, ew);
    k_wsplit<<<(DIN * 256 + 255) / 256, 256>>>(Wl1, Wr1, w1hi, w1lo, DIN * 256);
    k_wsplit<<<(HC * 256 + 255) / 256, 256>>>(Wl2, Wr2, w2hi, w2lo, HC * 256);

    // layer 1
    k_gemm<DIN, 1, 0><<<ROWS / 128, 256, smem1>>>(x, w1hi, w1lo);
    k_edge<0><<<NN * 2, 256>>>(We1, att1, b1, nullptr);

    // layer 2
    k_gemm<HC, 0, 1><<<ROWS / 128, 256, smem2>>>(nullptr, w2hi, w2lo);
    k_edge<1><<<NN * 2, 256>>>(We2, att2, b2, out);
}

// round 12
// speedup vs baseline: 1.1940x; 1.1940x over previous
#include <cuda_runtime.h>
#include <cuda_bf16.h>
#include <cstdint>
#include <math.h>

#define MM   16          // B*T
#define NN   5000
#define DIN  64
#define EE   80000
#define HC   128
#define E2   (EE + NN)   // 85000 with self loops
#define ROWS (MM * NN)   // 80000

// ---------------- scratch (no allocations allowed) ----------------
// feature buffers are NODE-major: row = n*MM + m
__device__ float g_xl[ROWS * HC];   // 41 MB
__device__ float g_xr[ROWS * HC];
__device__ float g_h [ROWS * HC];   // layer-1 output (node-major)
__device__ int   g_cnt[NN];
__device__ float g_wsum[NN];
__device__ int   g_rowoff[NN + 1];
__device__ int   g_fill[NN];
__device__ float g_selfw[NN];
__device__ int2  g_epk[E2];         // {src, bitcast(weight)}
// pre-split weights: [K x 256] = [Wl | Wr] in bf16 hi/lo
__device__ __nv_bfloat16 g_W1hi[DIN * 256], g_W1lo[DIN * 256];
__device__ __nv_bfloat16 g_W2hi[HC * 256],  g_W2lo[HC * 256];

// ---------------- preprocessing ----------------
__global__ void k_zero() {
    int i = blockIdx.x * blockDim.x + threadIdx.x;
    if (i < NN) { g_cnt[i] = 0; g_wsum[i] = 0.f; }
}

__global__ void k_deg(const int* __restrict__ ei, const float* __restrict__ ew) {
    int e = blockIdx.x * blockDim.x + threadIdx.x;
    if (e < EE) {
        int d = ei[EE + e];
        atomicAdd(&g_cnt[d], 1);
        atomicAdd(&g_wsum[d], ew[e]);
    }
}

// one block, 1024 threads: exclusive scan of (deg+1), self-loop weights
__global__ void k_scan() {
    __shared__ int sums[1024];
    int tid = threadIdx.x;
    int base = tid * 5;
    int loc[5];
    int s = 0;
#pragma unroll
    for (int j = 0; j < 5; j++) {
        int i = base + j;
        int d = (i < NN) ? (g_cnt[i] + 1) : 0;   // +1 for self loop
        loc[j] = s;
        s += d;
    }
    sums[tid] = s;
    __syncthreads();
    for (int off = 1; off < 1024; off <<= 1) {
        int v = (tid >= off) ? sums[tid - off] : 0;
        __syncthreads();
        sums[tid] += v;
        __syncthreads();
    }
    int excl = (tid == 0) ? 0 : sums[tid - 1];
#pragma unroll
    for (int j = 0; j < 5; j++) {
        int i = base + j;
        if (i < NN) {
            int o = excl + loc[j];
            g_rowoff[i] = o;
            g_fill[i]   = o;
            int c = g_cnt[i];
            g_selfw[i] = (c > 0) ? (g_wsum[i] / (float)c) : 0.f;
        }
    }
    if (tid == 1023) g_rowoff[NN] = sums[1023];
}

__global__ void k_scatter(const int* __restrict__ ei, const float* __restrict__ ew) {
    int i = blockIdx.x * blockDim.x + threadIdx.x;
    if (i < EE) {
        int d = ei[EE + i];
        int p = atomicAdd(&g_fill[d], 1);
        g_epk[p] = make_int2(ei[i], __float_as_int(ew[i]));
    } else if (i < E2) {
        int n = i - EE;
        int p = atomicAdd(&g_fill[n], 1);
        g_epk[p] = make_int2(n, __float_as_int(g_selfw[n]));
    }
}

// split [Wl | Wr] (each K x 128 fp32) into bf16 hi/lo [K x 256]
__global__ void k_wsplit(const float* __restrict__ Wl, const float* __restrict__ Wr,
                         __nv_bfloat16* __restrict__ hi, __nv_bfloat16* __restrict__ lo,
                         int total) {
    int i = blockIdx.x * blockDim.x + threadIdx.x;
    if (i >= total) return;
    int k = i >> 8;
    int n = i & 255;
    float v = (n < 128) ? Wl[(size_t)k * 128 + n] : Wr[(size_t)k * 128 + (n - 128)];
    __nv_bfloat16 h = __float2bfloat16(v);
    hi[i] = h;
    lo[i] = __float2bfloat16(v - __bfloat162float(h));
}

// ---------------- tensor-core helpers ----------------
__device__ __forceinline__ void ldsm4(unsigned* r, unsigned addr) {
    asm volatile("ldmatrix.sync.aligned.m8n8.x4.shared.b16 {%0,%1,%2,%3}, [%4];"
        : "=r"(r[0]), "=r"(r[1]), "=r"(r[2]), "=r"(r[3]) : "r"(addr));
}
__device__ __forceinline__ void ldsm4t(unsigned* r, unsigned addr) {
    asm volatile("ldmatrix.sync.aligned.m8n8.x4.trans.shared.b16 {%0,%1,%2,%3}, [%4];"
        : "=r"(r[0]), "=r"(r[1]), "=r"(r[2]), "=r"(r[3]) : "r"(addr));
}
__device__ __forceinline__ void mma_bf16(float* c, const unsigned* a, const unsigned* b) {
    asm volatile(
        "mma.sync.aligned.m16n8k16.row.col.f32.bf16.bf16.f32 "
        "{%0,%1,%2,%3}, {%4,%5,%6,%7}, {%8,%9}, {%0,%1,%2,%3};"
        : "+f"(c[0]), "+f"(c[1]), "+f"(c[2]), "+f"(c[3])
        : "r"(a[0]), "r"(a[1]), "r"(a[2]), "r"(a[3]), "r"(b[0]), "r"(b[1]));
}
__device__ __forceinline__ void bsplit(float x, __nv_bfloat16& h, __nv_bfloat16& l) {
    h = __float2bfloat16(x);
    l = __float2bfloat16(x - __bfloat162float(h));
}
__device__ __forceinline__ float lrelu(float t) { return fmaxf(t, 0.2f * t); }

// ---------------- projections: [xl | xr] = A @ [Wl | Wr] ----------------
// Tensor-core GEMM, bf16 2-term split (3 MMAs: hh + hl + lh) ~= fp32 accuracy.
// B comes pre-split in bf16 (g_W*hi/lo): staging is pure 16B copies, no cvt.
// Block: 32 rows x 256 cols, 256 threads (8 warps). Warp: 16 rows x 64 cols.
// MAP==1: A rows are (m*NN+n) (raw x) -> output row n*MM+m. IN_H: read g_h.
#define ASTR 40
#define BSTR 264
template <int K, int MAP, int IN_H>
__global__ void __launch_bounds__(256) k_gemm(const float* __restrict__ Ain,
                                              const __nv_bfloat16* __restrict__ Whi,
                                              const __nv_bfloat16* __restrict__ Wlo) {
    __shared__ __nv_bfloat16 As_hi[32 * ASTR];
    __shared__ __nv_bfloat16 As_lo[32 * ASTR];
    __shared__ __nv_bfloat16 Bs_hi[32 * BSTR];
    __shared__ __nv_bfloat16 Bs_lo[32 * BSTR];

    const float* __restrict__ A = IN_H ? (const float*)g_h : Ain;

    const int tid  = threadIdx.x;
    const int lane = tid & 31;
    const int w    = tid >> 5;
    const int mt   = w & 1;        // m-tile: rows mt*16..+15 of the 32
    const int nq   = w >> 1;       // n-quarter: cols nq*64..+63 of the 256
    const int row0 = blockIdx.x * 32;

    const unsigned ah_base = (unsigned)__cvta_generic_to_shared(As_hi);
    const unsigned al_base = (unsigned)__cvta_generic_to_shared(As_lo);
    const unsigned bh_base = (unsigned)__cvta_generic_to_shared(Bs_hi);
    const unsigned bl_base = (unsigned)__cvta_generic_to_shared(Bs_lo);

    float acc[8][4];
#pragma unroll
    for (int j = 0; j < 8; j++)
#pragma unroll
        for (int q = 0; q < 4; q++) acc[j][q] = 0.f;

    // staging maps
    const int sar = tid >> 3;            // A row 0..31
    const int sak = (tid & 7) * 4;       // A k-offset
    const unsigned a_row = (unsigned)(mt * 16 + (lane & 15));
    const unsigned a_coladd = (unsigned)((lane >> 4) << 3);
    const int bk_row = (lane & 7) + ((lane >> 3) & 1) * 8;
    const int b_nadd = (lane >> 4) << 3;

    for (int kc = 0; kc < K; kc += 32) {
        // ---- stage A chunk 32x32, split hi/lo ----
        {
            float4 v = *(const float4*)&A[(size_t)(row0 + sar) * K + kc + sak];
            __nv_bfloat16 h0, l0, h1, l1, h2, l2, h3, l3;
            bsplit(v.x, h0, l0); bsplit(v.y, h1, l1);
            bsplit(v.z, h2, l2); bsplit(v.w, h3, l3);
            __nv_bfloat16* ph = &As_hi[sar * ASTR + sak];
            __nv_bfloat16* pl = &As_lo[sar * ASTR + sak];
            ph[0] = h0; ph[1] = h1; ph[2] = h2; ph[3] = h3;
            pl[0] = l0; pl[1] = l1; pl[2] = l2; pl[3] = l3;
        }
        // ---- stage B chunk 32 x 256: pure 16-byte copies of pre-split bf16 ----
#pragma unroll
        for (int i = 0; i < 8; i++) {
            int idx = tid + i * 256;     // 0..2047 uint4 slots
            int arr = idx >> 10;         // 0: hi, 1: lo
            int rem = idx & 1023;
            int k   = rem >> 5;          // 0..31
            int c8  = (rem & 31) * 8;    // 0..248
            const __nv_bfloat16* src = (arr ? Wlo : Whi) + (size_t)(kc + k) * 256 + c8;
            __nv_bfloat16* dst = (arr ? Bs_lo : Bs_hi) + k * BSTR + c8;
            *(uint4*)dst = *(const uint4*)src;
        }
        __syncthreads();

        // ---- compute: 2 k16 steps ----
#pragma unroll
        for (int kk = 0; kk < 32; kk += 16) {
            unsigned ah[4], al[4];
            unsigned aoff = (a_row * ASTR + (unsigned)kk + a_coladd) * 2u;
            ldsm4(ah, ah_base + aoff);
            ldsm4(al, al_base + aoff);

            unsigned bh[16], bl[16];
#pragma unroll
            for (int t2 = 0; t2 < 4; t2++) {
                unsigned boff = ((unsigned)((kk + bk_row) * BSTR + nq * 64 + t2 * 16 + b_nadd)) * 2u;
                ldsm4t(&bh[t2 * 4], bh_base + boff);
                ldsm4t(&bl[t2 * 4], bl_base + boff);
            }
#pragma unroll
            for (int j = 0; j < 8; j++) {
                const unsigned* bhj = &bh[(j >> 1) * 4 + (j & 1) * 2];
                const unsigned* blj = &bl[(j >> 1) * 4 + (j & 1) * 2];
                mma_bf16(acc[j], ah, bhj);   // hi*hi
                mma_bf16(acc[j], ah, blj);   // hi*lo
                mma_bf16(acc[j], al, bhj);   // lo*hi
            }
        }
        __syncthreads();
    }

    // ---- epilogue ----
    int lrow = mt * 16 + (lane >> 2);
    int lcol = 2 * (lane & 3);
#pragma unroll
    for (int half = 0; half < 2; half++) {
        int r = row0 + lrow + half * 8;
        int orow;
        if (MAP == 1) {
            int m = r / NN;
            int n = r - m * NN;
            orow  = n * MM + m;
        } else {
            orow = r;
        }
#pragma unroll
        for (int j = 0; j < 8; j++) {
            int c = nq * 64 + j * 8 + lcol;
            float* buf = (c < 128) ? g_xl : g_xr;
            int cc = (c < 128) ? c : c - 128;
            *(float2*)&buf[(size_t)orow * HC + cc] =
                make_float2(acc[j][half * 2], acc[j][half * 2 + 1]);
        }
    }
}

// ---------------- fused edge kernel: gather + online softmax + aggregate ----------------
// One block per dst (grid NN, 8 warps). Each warp handles TWO m's:
// lanes 0-15 -> m = 2*warp, lanes 16-31 -> m = 2*warp+1.
// Each lane owns 8 contiguous channels ((lane&15)*8): head = channel/64, so
// each head spans 8 lanes -> 3-step shuffle reduction. Dual-state unroll.
template <int LAYER2>
__global__ void __launch_bounds__(256) k_edge(const float* __restrict__ We,
                                              const float* __restrict__ att,
                                              const float* __restrict__ bias,
                                              float* __restrict__ out) {
    int warp = threadIdx.x >> 5;
    int lane = threadIdx.x & 31;
    int dst  = blockIdx.x;
    int m    = (warp << 1) | (lane >> 4);
    int ch   = (lane & 15) << 3;      // channel base, 8 channels per lane

    float xi[8], we[8], at[8];
    {
        const float* p = &g_xr[(size_t)(dst * MM + m) * HC + ch];
        *(float4*)&xi[0] = *(const float4*)p;
        *(float4*)&xi[4] = *(const float4*)(p + 4);
        *(float4*)&we[0] = *(const float4*)&We[ch];
        *(float4*)&we[4] = *(const float4*)&We[ch + 4];
        *(float4*)&at[0] = *(const float4*)&att[ch];
        *(float4*)&at[4] = *(const float4*)&att[ch + 4];
    }

    // dual softmax states
    float accA[8], accB[8];
#pragma unroll
    for (int i = 0; i < 8; i++) { accA[i] = 0.f; accB[i] = 0.f; }
    float mxA = -1e30f, dnA = 0.f;
    float mxB = -1e30f, dnB = 0.f;

    int beg = g_rowoff[dst];
    int end = g_rowoff[dst + 1];

    int j = beg;
    for (; j + 1 < end; j += 2) {
        int2 eA = g_epk[j];
        int2 eB = g_epk[j + 1];
        float wA = __int_as_float(eA.y);
        float wB = __int_as_float(eB.y);
        float xjA[8], xjB[8];
        {
            const float* pA = &g_xl[(size_t)(eA.x * MM + m) * HC + ch];
            const float* pB = &g_xl[(size_t)(eB.x * MM + m) * HC + ch];
            *(float4*)&xjA[0] = *(const float4*)pA;
            *(float4*)&xjA[4] = *(const float4*)(pA + 4);
            *(float4*)&xjB[0] = *(const float4*)pB;
            *(float4*)&xjB[4] = *(const float4*)(pB + 4);
        }

        float pA = 0.f, pB = 0.f;
#pragma unroll
        for (int i = 0; i < 8; i++) {
            pA = fmaf(lrelu(fmaf(wA, we[i], xi[i] + xjA[i])), at[i], pA);
            pB = fmaf(lrelu(fmaf(wB, we[i], xi[i] + xjB[i])), at[i], pB);
        }
        // 3-step reduction within 8-lane head groups (both states interleave)
#pragma unroll
        for (int off = 1; off <= 4; off <<= 1) {
            pA += __shfl_xor_sync(0xffffffffu, pA, off);
            pB += __shfl_xor_sync(0xffffffffu, pB, off);
        }

        float nmA = fmaxf(mxA, pA);
        float nmB = fmaxf(mxB, pB);
        float scA = __expf(mxA - nmA);
        float scB = __expf(mxB - nmB);
        float eA_ = __expf(pA - nmA);
        float eB_ = __expf(pB - nmB);
        dnA = dnA * scA + eA_;
        dnB = dnB * scB + eB_;
#pragma unroll
        for (int i = 0; i < 8; i++) {
            accA[i] = fmaf(eA_, xjA[i], accA[i] * scA);
            accB[i] = fmaf(eB_, xjB[i], accB[i] * scB);
        }
        mxA = nmA;  mxB = nmB;
    }
    if (j < end) {
        int2 eA = g_epk[j];
        float wA = __int_as_float(eA.y);
        float xjA[8];
        const float* pAp = &g_xl[(size_t)(eA.x * MM + m) * HC + ch];
        *(float4*)&xjA[0] = *(const float4*)pAp;
        *(float4*)&xjA[4] = *(const float4*)(pAp + 4);
        float pA = 0.f;
#pragma unroll
        for (int i = 0; i < 8; i++)
            pA = fmaf(lrelu(fmaf(wA, we[i], xi[i] + xjA[i])), at[i], pA);
#pragma unroll
        for (int off = 1; off <= 4; off <<= 1)
            pA += __shfl_xor_sync(0xffffffffu, pA, off);
        float nmA = fmaxf(mxA, pA);
        float scA = __expf(mxA - nmA);
        float eA_ = __expf(pA - nmA);
        dnA = dnA * scA + eA_;
#pragma unroll
        for (int i = 0; i < 8; i++)
            accA[i] = fmaf(eA_, xjA[i], accA[i] * scA);
        mxA = nmA;
    }

    // merge state B into A (B may be empty: dnB=0 contributes nothing)
    float nm = fmaxf(mxA, mxB);
    float sA = __expf(mxA - nm);
    float sB = __expf(mxB - nm);
    float dn = dnA * sA + dnB * sB;
    float inv = 1.f / (dn + 1e-16f);

    float o[8];
#pragma unroll
    for (int i = 0; i < 8; i++) {
        float v = (accA[i] * sA + accB[i] * sB) * inv + bias[ch + i];
        o[i] = (v > 0.f) ? v : (__expf(v) - 1.f);   // ELU
    }

    float* dstp = LAYER2 ? &out[(size_t)(m * NN + dst) * HC + ch]
                         : &g_h[(size_t)(dst * MM + m) * HC + ch];
    *(float4*)dstp       = *(float4*)&o[0];
    *(float4*)(dstp + 4) = *(float4*)&o[4];
}

// ---------------- launch ----------------
extern "C" void kernel_launch(void* const* d_in, const int* in_sizes, int n_in,
                              void* d_out, int out_size) {
    const float* x    = (const float*)d_in[0];
    const int*   ei   = (const int*)d_in[1];
    const float* ew   = (const float*)d_in[2];
    const float* Wl1  = (const float*)d_in[3];
    const float* Wr1  = (const float*)d_in[4];
    const float* att1 = (const float*)d_in[5];
    const float* We1  = (const float*)d_in[6];
    const float* b1   = (const float*)d_in[7];
    const float* Wl2  = (const float*)d_in[8];
    const float* Wr2  = (const float*)d_in[9];
    const float* att2 = (const float*)d_in[10];
    const float* We2  = (const float*)d_in[11];
    const float* b2   = (const float*)d_in[12];
    float* out = (float*)d_out;

    __nv_bfloat16 *w1hi, *w1lo, *w2hi, *w2lo;
    cudaGetSymbolAddress((void**)&w1hi, g_W1hi);
    cudaGetSymbolAddress((void**)&w1lo, g_W1lo);
    cudaGetSymbolAddress((void**)&w2hi, g_W2hi);
    cudaGetSymbolAddress((void**)&w2lo, g_W2lo);

    k_zero<<<(NN + 255) / 256, 256>>>();
    k_deg<<<(EE + 255) / 256, 256>>>(ei, ew);
    k_scan<<<1, 1024>>>();
    k_scatter<<<(E2 + 255) / 256, 256>>>(ei, ew);
    k_wsplit<<<(DIN * 256 + 255) / 256, 256>>>(Wl1, Wr1, w1hi, w1lo, DIN * 256);
    k_wsplit<<<(HC * 256 + 255) / 256, 256>>>(Wl2, Wr2, w2hi, w2lo, HC * 256);

    // layer 1
    k_gemm<DIN, 1, 0><<<ROWS / 32, 256>>>(x, w1hi, w1lo);
    k_edge<0><<<NN, 256>>>(We1, att1, b1, nullptr);

    // layer 2
    k_gemm<HC, 0, 1><<<ROWS / 32, 256>>>(nullptr, w2hi, w2lo);
    k_edge<1><<<NN, 256>>>(We2, att2, b2, out);
}